// round 14
// baseline (speedup 1.0000x reference)
#include <cuda_runtime.h>
#include <math.h>
#include <stdint.h>

#define MAXN 8192
#define CHUNK 1024              // columns per pipeline chunk (4KB per array)
#define STAGES 3

__device__ float4 g_pts[MAXN];      // x, y, z, sq
__device__ double g_sum;
__device__ unsigned int g_done;

// ---------------- cp.async helpers ----------------
__device__ __forceinline__ void cp_async16(uint32_t smem_addr, const void* g) {
    asm volatile("cp.async.cg.shared.global [%0], [%1], 16;" :: "r"(smem_addr), "l"(g));
}
__device__ __forceinline__ void cp_commit() {
    asm volatile("cp.async.commit_group;" ::: "memory");
}
__device__ __forceinline__ void cp_wait2() {
    asm volatile("cp.async.wait_group 2;" ::: "memory");
}

// ---------------- block reduce (fp32 warp tree -> double) + completion ticket ----------------
__device__ __forceinline__ void commitBlock(float v, float* out) {
    #pragma unroll
    for (int o = 16; o > 0; o >>= 1)
        v += __shfl_down_sync(0xffffffffu, v, o);
    __shared__ double ws[8];
    int lane = threadIdx.x & 31;
    int warp = threadIdx.x >> 5;
    if (lane == 0) ws[warp] = (double)v;
    __syncthreads();
    if (threadIdx.x == 0) {
        double t = 0.0;
        int nw = (blockDim.x + 31) >> 5;
        for (int i = 0; i < nw; i++) t += ws[i];
        atomicAdd(&g_sum, t);
        __threadfence();
        unsigned int k = atomicAdd(&g_done, 1u);
        if (k == gridDim.x - 1u) {
            double s = *((volatile double*)&g_sum);
            out[0] = (float)s;
        }
    }
}

// ---------------- pack points + zero accumulators ----------------
__global__ void k_pack(const float* __restrict__ x, int n) {
    int i = blockIdx.x * blockDim.x + threadIdx.x;
    if (i == 0) { g_sum = 0.0; g_done = 0u; }
    if (i < n) {
        float a = x[3 * i + 0];
        float b = x[3 * i + 1];
        float c = x[3 * i + 2];
        float sq = __fadd_rn(__fadd_rn(__fmul_rn(a, a), __fmul_rn(b, b)), __fmul_rn(c, c));
        g_pts[i] = make_float4(a, b, c, sq);
    }
}

// ---------------- nonbonded per-element term ----------------
__device__ __forceinline__ float nb_term(float4 pi, float4 pj, float ep, float rm, float kq) {
    float dt  = fmaf(pi.z, pj.z, fmaf(pi.y, pj.y, pi.x * pj.x));
    float d2  = fmaf(-2.0f, dt, pi.w + pj.w);
    d2 = fmaxf(d2, 1e-12f);
    float inv = rsqrtf(d2);               // MUFU.RSQ
    float rod = rm * inv;
    float r2  = rod * rod;
    float r4  = r2 * r2;
    float r6  = r4 * r2;
    float vdw = ep * fmaf(r6, r6, -2.0f * r6);   // eps*(r12 - 2 r6)
    return fmaf(kq, inv, vdw);                   // + kqq/dist
}

// ---------------- bonded helpers ----------------
__device__ __forceinline__ float f3norm(float x, float y, float z) {
    return sqrtf(x * x + y * y + z * z);
}

__device__ __forceinline__ float torsion_angle(int a, int b, int c, int d) {
    float4 pa = g_pts[a], pb = g_pts[b], pc = g_pts[c], pd = g_pts[d];
    float abx = pb.x - pa.x, aby = pb.y - pa.y, abz = pb.z - pa.z;
    float bcx = pc.x - pb.x, bcy = pc.y - pb.y, bcz = pc.z - pb.z;
    float cdx = pd.x - pc.x, cdy = pd.y - pc.y, cdz = pd.z - pc.z;
    float n1x = aby * bcz - abz * bcy;
    float n1y = abz * bcx - abx * bcz;
    float n1z = abx * bcy - aby * bcx;
    float n2x = bcy * cdz - bcz * cdy;
    float n2y = bcz * cdx - bcx * cdz;
    float n2z = bcx * cdy - bcy * cdx;
    float num = n1x * n2x + n1y * n2y + n1z * n2z;
    float den = f3norm(n1x, n1y, n1z) * f3norm(n2x, n2y, n2z);
    float cosd = num / den;
    cosd = fminf(fmaxf(cosd, -0.9999f), 0.9999f);
    float ang = acosf(cosd);
    float cx = n1y * n2z - n1z * n2y;
    float cy = n1z * n2x - n1x * n2z;
    float cz = n1x * n2y - n1y * n2x;
    float sv = cx * bcx + cy * bcy + cz * bcz;
    float sgn = (float)(sv > 0.0f) - (float)(sv < 0.0f);
    return ang * sgn;
}

#define DEG2RAD 0.017453292519943295f

// ---------------- fused main kernel ----------------
// blocks [0, nbB)              : nonbonded rows b and nrows-1-b (cp.async pipeline)
// blocks [nbB, nbB+bondB)      : bonded terms
// block  nbB+bondB             : central restraint (flag-gated)
__global__ void __launch_bounds__(256) k_main(
    const float* __restrict__ eps, const float* __restrict__ rmin, const float* __restrict__ kqq, int n, int nbB,
    const int* __restrict__ bond, const float* __restrict__ kb, const float* __restrict__ b0, int nb,
    const int* __restrict__ ang,  const float* __restrict__ kt, const float* __restrict__ t0, int na,
    const int* __restrict__ ub,   const float* __restrict__ ku, const float* __restrict__ s0, int nu,
    const int* __restrict__ dih,  const float* __restrict__ kd, const float* __restrict__ nd, const float* __restrict__ d0, int ndh,
    const int* __restrict__ imp,  const float* __restrict__ kp, const float* __restrict__ p0, int ni,
    int bondB, const int* __restrict__ central,
    float* out)
{
    // [stage][array][elem]: 3 stages x 3 arrays x 1024 floats = 36 KB
    __shared__ __align__(16) float sbuf[STAGES][3][CHUNK];

    float acc = 0.0f;
    int tid = threadIdx.x;

    if (blockIdx.x < (unsigned)nbB) {
        int nrows = n - 1;
        int b = blockIdx.x;
        int rows[2];
        int nr = 1;
        rows[0] = b;
        int i2 = nrows - 1 - b;
        if (i2 > b) { rows[1] = i2; nr = 2; }

        // build chunk list: (row index into rows[], start column)
        int c_row[8], c_start[8];
        int nc = 0;
        for (int r = 0; r < nr; r++) {
            int i = rows[r];
            int ja0 = (i + 1) & ~3;           // 16B-aligned start col
            for (int s = ja0; s < n; s += CHUNK) {
                c_row[nc] = r;
                c_start[nc] = s;
                nc++;
            }
        }

        // ---- issue one chunk's loads (16B per thread) ----
        auto load_chunk = [&](int k, int st) {
            int i = rows[c_row[k]];
            int cs = c_start[k];
            int segs = (n - cs < CHUNK ? n - cs : CHUNK) >> 2;   // 16B segments
            if (tid < segs) {
                size_t go = (size_t)i * n + cs + (tid << 2);
                uint32_t sa = (uint32_t)__cvta_generic_to_shared(&sbuf[st][0][tid << 2]);
                cp_async16(sa,                 eps  + go);
                cp_async16(sa + 4096u,         rmin + go);
                cp_async16(sa + 8192u,         kqq  + go);
            }
        };

        // prologue: stages 0..STAGES-2
        int k_load = 0;
        for (; k_load < STAGES - 1; k_load++) {
            if (k_load < nc) load_chunk(k_load, k_load % STAGES);
            cp_commit();                      // empty group if out of chunks
        }

        for (int k = 0; k < nc; k++) {
            // issue chunk k+STAGES-1 (or empty group to keep wait count aligned)
            if (k_load < nc) load_chunk(k_load, k_load % STAGES);
            cp_commit();
            k_load++;

            cp_wait2();                       // chunk k's group complete
            __syncthreads();

            int st = k % STAGES;
            int i = rows[c_row[k]];
            int cs = c_start[k];
            float4 pi = g_pts[i];
            const float* sE = sbuf[st][0];
            const float* sR = sbuf[st][1];
            const float* sQ = sbuf[st][2];

            float a0 = 0.f, a1 = 0.f, a2 = 0.f, a3 = 0.f;
            int j0 = cs + tid;
            int j1 = j0 + 256, j2 = j0 + 512, j3 = j0 + 768;
            int lo = i + 1;
            if (j0 >= lo && j0 < n) a0 = nb_term(pi, g_pts[j0], sE[tid],       sR[tid],       sQ[tid]);
            if (j1 >= lo && j1 < n) a1 = nb_term(pi, g_pts[j1], sE[tid + 256], sR[tid + 256], sQ[tid + 256]);
            if (j2 >= lo && j2 < n) a2 = nb_term(pi, g_pts[j2], sE[tid + 512], sR[tid + 512], sQ[tid + 512]);
            if (j3 >= lo && j3 < n) a3 = nb_term(pi, g_pts[j3], sE[tid + 768], sR[tid + 768], sQ[tid + 768]);
            acc += (a0 + a1) + (a2 + a3);

            __syncthreads();                  // buffer free before re-load
        }
    } else if (blockIdx.x < (unsigned)(nbB + bondB)) {
        // ---- bonded ----
        int t = (blockIdx.x - nbB) * 256 + tid;
        if (t < nb) {
            int a = bond[2 * t], b = bond[2 * t + 1];
            float4 pa = g_pts[a], pb = g_pts[b];
            float d = f3norm(pa.x - pb.x, pa.y - pb.y, pa.z - pb.z);
            float dd = d - b0[t];
            acc += kb[t] * dd * dd;
        }
        if (t < na) {
            int a = ang[3 * t], b = ang[3 * t + 1], c = ang[3 * t + 2];
            float4 pa = g_pts[a], pb = g_pts[b], pc = g_pts[c];
            float bax = pa.x - pb.x, bay = pa.y - pb.y, baz = pa.z - pb.z;
            float bcx = pc.x - pb.x, bcy = pc.y - pb.y, bcz = pc.z - pb.z;
            float num = bax * bcx + bay * bcy + baz * bcz;
            float den = f3norm(bax, bay, baz) * f3norm(bcx, bcy, bcz);
            float ct = num / den;
            ct = fminf(fmaxf(ct, -0.9999f), 0.9999f);
            float th = acosf(ct) - t0[t] * DEG2RAD;
            acc += kt[t] * th * th;
        }
        if (t < nu) {
            int a = ub[2 * t], b = ub[2 * t + 1];
            float4 pa = g_pts[a], pb = g_pts[b];
            float d = f3norm(pa.x - pb.x, pa.y - pb.y, pa.z - pb.z);
            float dd = d - s0[t];
            acc += ku[t] * dd * dd;
        }
        if (t < ndh) {
            float delta = torsion_angle(dih[4 * t], dih[4 * t + 1], dih[4 * t + 2], dih[4 * t + 3]);
            acc += kd[t] * (1.0f + cosf(nd[t] * delta - d0[t] * DEG2RAD));
        }
        if (t < ni) {
            float psi = torsion_angle(imp[4 * t], imp[4 * t + 1], imp[4 * t + 2], imp[4 * t + 3]);
            float dd = psi - p0[t] * DEG2RAD;
            acc += kp[t] * dd * dd;
        }
    } else {
        // ---- central restraint (flag is 0 in this dataset, but stay correct) ----
        if (central[0] != 0) {
            float* rx = sbuf[0][0];
            float* ry = sbuf[0][1];
            float* rz = sbuf[0][2];
            float sx = 0.f, sy = 0.f, sz = 0.f;
            for (int i = tid; i < n; i += 256) {
                float4 p = g_pts[i];
                sx += p.x; sy += p.y; sz += p.z;
            }
            rx[tid] = sx; ry[tid] = sy; rz[tid] = sz;
            __syncthreads();
            for (int s = 128; s > 0; s >>= 1) {
                if (tid < s) {
                    rx[tid] += rx[tid + s];
                    ry[tid] += ry[tid + s];
                    rz[tid] += rz[tid + s];
                }
                __syncthreads();
            }
            float mx = rx[0] / (float)n, my = ry[0] / (float)n, mz = rz[0] / (float)n;
            for (int i = tid; i < n; i += 256) {
                float4 p = g_pts[i];
                float dx = p.x - mx, dy = p.y - my, dz = p.z - mz;
                acc += 0.1f * (dx * dx + dy * dy + dz * dz);
            }
        }
    }

    commitBlock(acc, out);
}

static inline int imax2(int a, int b) { return a > b ? a : b; }

extern "C" void kernel_launch(void* const* d_in, const int* in_sizes, int n_in,
                              void* d_out, int out_size) {
    const float* x    = (const float*)d_in[0];
    const float* kb   = (const float*)d_in[1];
    const float* b0   = (const float*)d_in[2];
    const float* kt   = (const float*)d_in[3];
    const float* t0   = (const float*)d_in[4];
    const float* ku   = (const float*)d_in[5];
    const float* s0   = (const float*)d_in[6];
    const float* kd   = (const float*)d_in[7];
    const float* nd   = (const float*)d_in[8];
    const float* d0   = (const float*)d_in[9];
    const float* kp   = (const float*)d_in[10];
    const float* p0   = (const float*)d_in[11];
    const float* eps  = (const float*)d_in[12];
    const float* rmin = (const float*)d_in[13];
    const float* kqq  = (const float*)d_in[14];
    const int* bond   = (const int*)d_in[15];
    const int* ang    = (const int*)d_in[16];
    const int* ub     = (const int*)d_in[17];
    const int* dih    = (const int*)d_in[18];
    const int* imp    = (const int*)d_in[19];
    const int* cen    = (const int*)d_in[20];

    int n   = in_sizes[0] / 3;
    int nb  = in_sizes[15] / 2;
    int na  = in_sizes[16] / 3;
    int nu  = in_sizes[17] / 2;
    int ndh = in_sizes[18] / 4;
    int ni  = in_sizes[19] / 4;

    k_pack<<<(n + 255) / 256, 256>>>(x, n);

    int nrows = n - 1;
    int nbB = (nrows + 1) / 2;
    int maxc = imax2(imax2(nb, na), imax2(nu, imax2(ndh, ni)));
    int bondB = (maxc + 255) / 256;
    int total = nbB + bondB + 1;

    k_main<<<total, 256>>>(eps, rmin, kqq, n, nbB,
                           bond, kb, b0, nb,
                           ang, kt, t0, na,
                           ub, ku, s0, nu,
                           dih, kd, nd, d0, ndh,
                           imp, kp, p0, ni,
                           bondB, cen,
                           (float*)d_out);
}

// round 15
// speedup vs baseline: 1.3821x; 1.3821x over previous
#include <cuda_runtime.h>
#include <math.h>
#include <stdint.h>

#define MAXN 8192

__device__ float4 g_pts[MAXN];      // x, y, z, sq
__device__ double g_sum;
__device__ unsigned int g_done;

// ---------------- L2 bulk prefetch (bulk-async engine, fire-and-forget) ----------------
__device__ __forceinline__ void l2_prefetch(const void* g, uint32_t bytes) {
    asm volatile("cp.async.bulk.prefetch.L2.global [%0], %1;" :: "l"(g), "r"(bytes) : "memory");
}

// ---------------- block reduce (fp32 warp tree -> double) + completion ticket ----------------
__device__ __forceinline__ void commitBlock(float v, float* out) {
    #pragma unroll
    for (int o = 16; o > 0; o >>= 1)
        v += __shfl_down_sync(0xffffffffu, v, o);
    __shared__ double ws[8];
    int lane = threadIdx.x & 31;
    int warp = threadIdx.x >> 5;
    if (lane == 0) ws[warp] = (double)v;
    __syncthreads();
    if (threadIdx.x == 0) {
        double t = 0.0;
        int nw = (blockDim.x + 31) >> 5;
        for (int i = 0; i < nw; i++) t += ws[i];
        atomicAdd(&g_sum, t);
        __threadfence();
        unsigned int k = atomicAdd(&g_done, 1u);
        if (k == gridDim.x - 1u) {
            double s = *((volatile double*)&g_sum);
            out[0] = (float)s;
        }
    }
}

// ---------------- pack points + zero accumulators ----------------
__global__ void k_pack(const float* __restrict__ x, int n) {
    int i = blockIdx.x * blockDim.x + threadIdx.x;
    if (i == 0) { g_sum = 0.0; g_done = 0u; }
    if (i < n) {
        float a = x[3 * i + 0];
        float b = x[3 * i + 1];
        float c = x[3 * i + 2];
        float sq = __fadd_rn(__fadd_rn(__fmul_rn(a, a), __fmul_rn(b, b)), __fmul_rn(c, c));
        g_pts[i] = make_float4(a, b, c, sq);
    }
}

// ---------------- nonbonded per-element term ----------------
__device__ __forceinline__ float nb_term(float4 pi, float4 pj, float ep, float rm, float kq) {
    float dt  = fmaf(pi.z, pj.z, fmaf(pi.y, pj.y, pi.x * pj.x));
    float d2  = fmaf(-2.0f, dt, pi.w + pj.w);
    d2 = fmaxf(d2, 1e-12f);
    float inv = rsqrtf(d2);               // MUFU.RSQ
    float rod = rm * inv;
    float r2  = rod * rod;
    float r4  = r2 * r2;
    float r6  = r4 * r2;
    float vdw = ep * fmaf(r6, r6, -2.0f * r6);   // eps*(r12 - 2 r6)
    return fmaf(kq, inv, vdw);                   // + kqq/dist
}

// ---------------- bonded helpers ----------------
__device__ __forceinline__ float f3norm(float x, float y, float z) {
    return sqrtf(x * x + y * y + z * z);
}

__device__ __forceinline__ float torsion_angle(int a, int b, int c, int d) {
    float4 pa = g_pts[a], pb = g_pts[b], pc = g_pts[c], pd = g_pts[d];
    float abx = pb.x - pa.x, aby = pb.y - pa.y, abz = pb.z - pa.z;
    float bcx = pc.x - pb.x, bcy = pc.y - pb.y, bcz = pc.z - pb.z;
    float cdx = pd.x - pc.x, cdy = pd.y - pc.y, cdz = pd.z - pc.z;
    float n1x = aby * bcz - abz * bcy;
    float n1y = abz * bcx - abx * bcz;
    float n1z = abx * bcy - aby * bcx;
    float n2x = bcy * cdz - bcz * cdy;
    float n2y = bcz * cdx - bcx * cdz;
    float n2z = bcx * cdy - bcy * cdx;
    float num = n1x * n2x + n1y * n2y + n1z * n2z;
    float den = f3norm(n1x, n1y, n1z) * f3norm(n2x, n2y, n2z);
    float cosd = num / den;
    cosd = fminf(fmaxf(cosd, -0.9999f), 0.9999f);
    float ang = acosf(cosd);
    float cx = n1y * n2z - n1z * n2y;
    float cy = n1z * n2x - n1x * n2z;
    float cz = n1x * n2y - n1y * n2x;
    float sv = cx * bcx + cy * bcy + cz * bcz;
    float sgn = (float)(sv > 0.0f) - (float)(sv < 0.0f);
    return ang * sgn;
}

#define DEG2RAD 0.017453292519943295f

// ---------------- fused main kernel ----------------
// blocks [0, nbB)              : nonbonded rows b and nrows-1-b
// blocks [nbB, nbB+bondB)      : bonded terms
// block  nbB+bondB             : central restraint (flag-gated)
__global__ void __launch_bounds__(256) k_main(
    const float* __restrict__ eps, const float* __restrict__ rmin, const float* __restrict__ kqq, int n, int nbB,
    const int* __restrict__ bond, const float* __restrict__ kb, const float* __restrict__ b0, int nb,
    const int* __restrict__ ang,  const float* __restrict__ kt, const float* __restrict__ t0, int na,
    const int* __restrict__ ub,   const float* __restrict__ ku, const float* __restrict__ s0, int nu,
    const int* __restrict__ dih,  const float* __restrict__ kd, const float* __restrict__ nd, const float* __restrict__ d0, int ndh,
    const int* __restrict__ imp,  const float* __restrict__ kp, const float* __restrict__ p0, int ni,
    int bondB, const int* __restrict__ central,
    float* out)
{
    float acc = 0.0f;
    int tid = threadIdx.x;

    if (blockIdx.x < (unsigned)nbB) {
        // ---- nonbonded: lane-contiguous columns, 4-way unroll, 4 accumulators,
        //      own-row L2 prefetch. Prefetch LONG row first; compute SHORT row
        //      first so the long row's prefetch gets lead time. ----
        int nrows = n - 1;
        int b = blockIdx.x;
        // rows[0] = b has the LONG suffix (n-1-b cols); rows[1] the short one.
        int rows[2];
        int nr = 1;
        rows[0] = b;
        int i2 = nrows - 1 - b;
        if (i2 > b) { rows[1] = i2; nr = 2; }

        if (tid == 0) {
            // issue long row first -> earliest in the engine queue
            for (int r = 0; r < nr; r++) {
                int i = rows[r];
                int ja0 = (i + 1) & ~3;
                uint32_t bytes = (uint32_t)(n - ja0) * 4u;
                if (bytes) {
                    size_t go = (size_t)i * n + ja0;
                    l2_prefetch(eps  + go, bytes);
                    l2_prefetch(rmin + go, bytes);
                    l2_prefetch(kqq  + go, bytes);
                }
            }
        }

        // compute short row first (rows[nr-1]), long row last
        for (int r = nr - 1; r >= 0; r--) {
            int i = rows[r];
            float4 pi = g_pts[i];
            const float* ep = eps  + (size_t)i * n;
            const float* rp = rmin + (size_t)i * n;
            const float* qp = kqq  + (size_t)i * n;

            float a0 = 0.f, a1 = 0.f, a2 = 0.f, a3 = 0.f;
            int j = i + 1 + tid;
            // 4 independent element chains, 16 loads in flight
            for (; j + 768 < n; j += 1024) {
                int j1 = j + 256, j2 = j + 512, j3 = j + 768;
                float e0 = __ldcs(ep + j),  e1 = __ldcs(ep + j1);
                float e2 = __ldcs(ep + j2), e3 = __ldcs(ep + j3);
                float r0 = __ldcs(rp + j),  r1 = __ldcs(rp + j1);
                float r2 = __ldcs(rp + j2), r3 = __ldcs(rp + j3);
                float q0 = __ldcs(qp + j),  q1 = __ldcs(qp + j1);
                float q2 = __ldcs(qp + j2), q3 = __ldcs(qp + j3);
                float4 p0j = g_pts[j];
                float4 p1j = g_pts[j1];
                float4 p2j = g_pts[j2];
                float4 p3j = g_pts[j3];
                a0 += nb_term(pi, p0j, e0, r0, q0);
                a1 += nb_term(pi, p1j, e1, r1, q1);
                a2 += nb_term(pi, p2j, e2, r2, q2);
                a3 += nb_term(pi, p3j, e3, r3, q3);
            }
            for (; j < n; j += 256)
                a0 += nb_term(pi, g_pts[j], __ldcs(ep + j), __ldcs(rp + j), __ldcs(qp + j));
            acc += (a0 + a1) + (a2 + a3);
        }
    } else if (blockIdx.x < (unsigned)(nbB + bondB)) {
        // ---- bonded ----
        int t = (blockIdx.x - nbB) * 256 + tid;
        if (t < nb) {
            int a = bond[2 * t], b = bond[2 * t + 1];
            float4 pa = g_pts[a], pb = g_pts[b];
            float d = f3norm(pa.x - pb.x, pa.y - pb.y, pa.z - pb.z);
            float dd = d - b0[t];
            acc += kb[t] * dd * dd;
        }
        if (t < na) {
            int a = ang[3 * t], b = ang[3 * t + 1], c = ang[3 * t + 2];
            float4 pa = g_pts[a], pb = g_pts[b], pc = g_pts[c];
            float bax = pa.x - pb.x, bay = pa.y - pb.y, baz = pa.z - pb.z;
            float bcx = pc.x - pb.x, bcy = pc.y - pb.y, bcz = pc.z - pb.z;
            float num = bax * bcx + bay * bcy + baz * bcz;
            float den = f3norm(bax, bay, baz) * f3norm(bcx, bcy, bcz);
            float ct = num / den;
            ct = fminf(fmaxf(ct, -0.9999f), 0.9999f);
            float th = acosf(ct) - t0[t] * DEG2RAD;
            acc += kt[t] * th * th;
        }
        if (t < nu) {
            int a = ub[2 * t], b = ub[2 * t + 1];
            float4 pa = g_pts[a], pb = g_pts[b];
            float d = f3norm(pa.x - pb.x, pa.y - pb.y, pa.z - pb.z);
            float dd = d - s0[t];
            acc += ku[t] * dd * dd;
        }
        if (t < ndh) {
            float delta = torsion_angle(dih[4 * t], dih[4 * t + 1], dih[4 * t + 2], dih[4 * t + 3]);
            acc += kd[t] * (1.0f + cosf(nd[t] * delta - d0[t] * DEG2RAD));
        }
        if (t < ni) {
            float psi = torsion_angle(imp[4 * t], imp[4 * t + 1], imp[4 * t + 2], imp[4 * t + 3]);
            float dd = psi - p0[t] * DEG2RAD;
            acc += kp[t] * dd * dd;
        }
    } else {
        // ---- central restraint (flag is 0 in this dataset, but stay correct) ----
        if (central[0] != 0) {
            __shared__ float rx[256], ry[256], rz[256];
            float sx = 0.f, sy = 0.f, sz = 0.f;
            for (int i = tid; i < n; i += 256) {
                float4 p = g_pts[i];
                sx += p.x; sy += p.y; sz += p.z;
            }
            rx[tid] = sx; ry[tid] = sy; rz[tid] = sz;
            __syncthreads();
            for (int s = 128; s > 0; s >>= 1) {
                if (tid < s) {
                    rx[tid] += rx[tid + s];
                    ry[tid] += ry[tid + s];
                    rz[tid] += rz[tid + s];
                }
                __syncthreads();
            }
            float mx = rx[0] / (float)n, my = ry[0] / (float)n, mz = rz[0] / (float)n;
            for (int i = tid; i < n; i += 256) {
                float4 p = g_pts[i];
                float dx = p.x - mx, dy = p.y - my, dz = p.z - mz;
                acc += 0.1f * (dx * dx + dy * dy + dz * dz);
            }
        }
    }

    commitBlock(acc, out);
}

static inline int imax2(int a, int b) { return a > b ? a : b; }

extern "C" void kernel_launch(void* const* d_in, const int* in_sizes, int n_in,
                              void* d_out, int out_size) {
    const float* x    = (const float*)d_in[0];
    const float* kb   = (const float*)d_in[1];
    const float* b0   = (const float*)d_in[2];
    const float* kt   = (const float*)d_in[3];
    const float* t0   = (const float*)d_in[4];
    const float* ku   = (const float*)d_in[5];
    const float* s0   = (const float*)d_in[6];
    const float* kd   = (const float*)d_in[7];
    const float* nd   = (const float*)d_in[8];
    const float* d0   = (const float*)d_in[9];
    const float* kp   = (const float*)d_in[10];
    const float* p0   = (const float*)d_in[11];
    const float* eps  = (const float*)d_in[12];
    const float* rmin = (const float*)d_in[13];
    const float* kqq  = (const float*)d_in[14];
    const int* bond   = (const int*)d_in[15];
    const int* ang    = (const int*)d_in[16];
    const int* ub     = (const int*)d_in[17];
    const int* dih    = (const int*)d_in[18];
    const int* imp    = (const int*)d_in[19];
    const int* cen    = (const int*)d_in[20];

    int n   = in_sizes[0] / 3;
    int nb  = in_sizes[15] / 2;
    int na  = in_sizes[16] / 3;
    int nu  = in_sizes[17] / 2;
    int ndh = in_sizes[18] / 4;
    int ni  = in_sizes[19] / 4;

    k_pack<<<(n + 255) / 256, 256>>>(x, n);

    int nrows = n - 1;
    int nbB = (nrows + 1) / 2;
    int maxc = imax2(imax2(nb, na), imax2(nu, imax2(ndh, ni)));
    int bondB = (maxc + 255) / 256;
    int total = nbB + bondB + 1;

    k_main<<<total, 256>>>(eps, rmin, kqq, n, nbB,
                           bond, kb, b0, nb,
                           ang, kt, t0, na,
                           ub, ku, s0, nu,
                           dih, kd, nd, d0, ndh,
                           imp, kp, p0, ni,
                           bondB, cen,
                           (float*)d_out);
}

// round 16
// speedup vs baseline: 1.6327x; 1.1813x over previous
#include <cuda_runtime.h>
#include <math.h>
#include <stdint.h>

#define MAXN 8192

__device__ float4 g_pts[MAXN];      // x, y, z, sq
__device__ double g_sum;
__device__ unsigned int g_done;

// ---------------- L2 bulk prefetch (bulk-async engine, no LDG queue slot) ----------------
__device__ __forceinline__ void l2_prefetch(const void* g, uint32_t bytes) {
    asm volatile("cp.async.bulk.prefetch.L2.global [%0], %1;" :: "l"(g), "r"(bytes) : "memory");
}

// ---------------- block reduce (fp32 warp tree -> double) + completion ticket ----------------
__device__ __forceinline__ void commitBlock(float v, float* out) {
    #pragma unroll
    for (int o = 16; o > 0; o >>= 1)
        v += __shfl_down_sync(0xffffffffu, v, o);
    __shared__ double ws[8];
    int lane = threadIdx.x & 31;
    int warp = threadIdx.x >> 5;
    if (lane == 0) ws[warp] = (double)v;
    __syncthreads();
    if (threadIdx.x == 0) {
        double t = 0.0;
        int nw = (blockDim.x + 31) >> 5;
        for (int i = 0; i < nw; i++) t += ws[i];
        atomicAdd(&g_sum, t);
        __threadfence();
        unsigned int k = atomicAdd(&g_done, 1u);
        if (k == gridDim.x - 1u) {
            double s = *((volatile double*)&g_sum);
            out[0] = (float)s;
        }
    }
}

// ---------------- pack points + zero accumulators ----------------
__global__ void k_pack(const float* __restrict__ x, int n) {
    int i = blockIdx.x * blockDim.x + threadIdx.x;
    if (i == 0) { g_sum = 0.0; g_done = 0u; }
    if (i < n) {
        float a = x[3 * i + 0];
        float b = x[3 * i + 1];
        float c = x[3 * i + 2];
        float sq = __fadd_rn(__fadd_rn(__fmul_rn(a, a), __fmul_rn(b, b)), __fmul_rn(c, c));
        g_pts[i] = make_float4(a, b, c, sq);
    }
}

// ---------------- nonbonded per-element term ----------------
__device__ __forceinline__ float nb_term(float4 pi, float4 pj, float ep, float rm, float kq) {
    float dt  = fmaf(pi.z, pj.z, fmaf(pi.y, pj.y, pi.x * pj.x));
    float d2  = fmaf(-2.0f, dt, pi.w + pj.w);
    d2 = fmaxf(d2, 1e-12f);
    float inv = rsqrtf(d2);               // MUFU.RSQ
    float rod = rm * inv;
    float r2  = rod * rod;
    float r4  = r2 * r2;
    float r6  = r4 * r2;
    float vdw = ep * fmaf(r6, r6, -2.0f * r6);   // eps*(r12 - 2 r6)
    return fmaf(kq, inv, vdw);                   // + kqq/dist
}

// ---------------- bonded helpers ----------------
__device__ __forceinline__ float f3norm(float x, float y, float z) {
    return sqrtf(x * x + y * y + z * z);
}

__device__ __forceinline__ float torsion_angle(int a, int b, int c, int d) {
    float4 pa = g_pts[a], pb = g_pts[b], pc = g_pts[c], pd = g_pts[d];
    float abx = pb.x - pa.x, aby = pb.y - pa.y, abz = pb.z - pa.z;
    float bcx = pc.x - pb.x, bcy = pc.y - pb.y, bcz = pc.z - pb.z;
    float cdx = pd.x - pc.x, cdy = pd.y - pc.y, cdz = pd.z - pc.z;
    float n1x = aby * bcz - abz * bcy;
    float n1y = abz * bcx - abx * bcz;
    float n1z = abx * bcy - aby * bcx;
    float n2x = bcy * cdz - bcz * cdy;
    float n2y = bcz * cdx - bcx * cdz;
    float n2z = bcx * cdy - bcy * cdx;
    float num = n1x * n2x + n1y * n2y + n1z * n2z;
    float den = f3norm(n1x, n1y, n1z) * f3norm(n2x, n2y, n2z);
    float cosd = num / den;
    cosd = fminf(fmaxf(cosd, -0.9999f), 0.9999f);
    float ang = acosf(cosd);
    float cx = n1y * n2z - n1z * n2y;
    float cy = n1z * n2x - n1x * n2z;
    float cz = n1x * n2y - n1y * n2x;
    float sv = cx * bcx + cy * bcy + cz * bcz;
    float sgn = (float)(sv > 0.0f) - (float)(sv < 0.0f);
    return ang * sgn;
}

#define DEG2RAD 0.017453292519943295f

// ---------------- fused main kernel ----------------
// blocks [0, nbB)              : nonbonded rows b and nrows-1-b
// blocks [nbB, nbB+bondB)      : bonded terms
// block  nbB+bondB             : central restraint (flag-gated)
__global__ void __launch_bounds__(256) k_main(
    const float* __restrict__ eps, const float* __restrict__ rmin, const float* __restrict__ kqq, int n, int nbB,
    const int* __restrict__ bond, const float* __restrict__ kb, const float* __restrict__ b0, int nb,
    const int* __restrict__ ang,  const float* __restrict__ kt, const float* __restrict__ t0, int na,
    const int* __restrict__ ub,   const float* __restrict__ ku, const float* __restrict__ s0, int nu,
    const int* __restrict__ dih,  const float* __restrict__ kd, const float* __restrict__ nd, const float* __restrict__ d0, int ndh,
    const int* __restrict__ imp,  const float* __restrict__ kp, const float* __restrict__ p0, int ni,
    int bondB, const int* __restrict__ central,
    float* out)
{
    float acc = 0.0f;
    int tid = threadIdx.x;

    if (blockIdx.x < (unsigned)nbB) {
        // ---- nonbonded: lane-contiguous columns, 4-way unroll, 4 accumulators,
        //      own-row L2 prefetch via bulk-async engine ----
        int nrows = n - 1;
        int b = blockIdx.x;
        int rows[2];
        int nr = 1;
        rows[0] = b;
        int i2 = nrows - 1 - b;
        if (i2 > b) { rows[1] = i2; nr = 2; }

        if (tid == 0) {
            for (int r = 0; r < nr; r++) {
                int i = rows[r];
                int ja0 = (i + 1) & ~3;                 // 16B-aligned start col
                uint32_t bytes = (uint32_t)(n - ja0) * 4u;
                if (bytes) {
                    size_t go = (size_t)i * n + ja0;
                    l2_prefetch(eps  + go, bytes);
                    l2_prefetch(rmin + go, bytes);
                    l2_prefetch(kqq  + go, bytes);
                }
            }
        }

        for (int r = 0; r < nr; r++) {
            int i = rows[r];
            float4 pi = g_pts[i];
            const float* ep = eps  + (size_t)i * n;
            const float* rp = rmin + (size_t)i * n;
            const float* qp = kqq  + (size_t)i * n;

            float a0 = 0.f, a1 = 0.f, a2 = 0.f, a3 = 0.f;
            int j = i + 1 + tid;
            // 4 independent element chains, 16 loads in flight
            for (; j + 768 < n; j += 1024) {
                int j1 = j + 256, j2 = j + 512, j3 = j + 768;
                float e0 = __ldcs(ep + j),  e1 = __ldcs(ep + j1);
                float e2 = __ldcs(ep + j2), e3 = __ldcs(ep + j3);
                float r0 = __ldcs(rp + j),  r1 = __ldcs(rp + j1);
                float r2 = __ldcs(rp + j2), r3 = __ldcs(rp + j3);
                float q0 = __ldcs(qp + j),  q1 = __ldcs(qp + j1);
                float q2 = __ldcs(qp + j2), q3 = __ldcs(qp + j3);
                float4 p0j = g_pts[j];
                float4 p1j = g_pts[j1];
                float4 p2j = g_pts[j2];
                float4 p3j = g_pts[j3];
                a0 += nb_term(pi, p0j, e0, r0, q0);
                a1 += nb_term(pi, p1j, e1, r1, q1);
                a2 += nb_term(pi, p2j, e2, r2, q2);
                a3 += nb_term(pi, p3j, e3, r3, q3);
            }
            for (; j < n; j += 256)
                a0 += nb_term(pi, g_pts[j], __ldcs(ep + j), __ldcs(rp + j), __ldcs(qp + j));
            acc += (a0 + a1) + (a2 + a3);
        }
    } else if (blockIdx.x < (unsigned)(nbB + bondB)) {
        // ---- bonded ----
        int t = (blockIdx.x - nbB) * 256 + tid;
        if (t < nb) {
            int a = bond[2 * t], b = bond[2 * t + 1];
            float4 pa = g_pts[a], pb = g_pts[b];
            float d = f3norm(pa.x - pb.x, pa.y - pb.y, pa.z - pb.z);
            float dd = d - b0[t];
            acc += kb[t] * dd * dd;
        }
        if (t < na) {
            int a = ang[3 * t], b = ang[3 * t + 1], c = ang[3 * t + 2];
            float4 pa = g_pts[a], pb = g_pts[b], pc = g_pts[c];
            float bax = pa.x - pb.x, bay = pa.y - pb.y, baz = pa.z - pb.z;
            float bcx = pc.x - pb.x, bcy = pc.y - pb.y, bcz = pc.z - pb.z;
            float num = bax * bcx + bay * bcy + baz * bcz;
            float den = f3norm(bax, bay, baz) * f3norm(bcx, bcy, bcz);
            float ct = num / den;
            ct = fminf(fmaxf(ct, -0.9999f), 0.9999f);
            float th = acosf(ct) - t0[t] * DEG2RAD;
            acc += kt[t] * th * th;
        }
        if (t < nu) {
            int a = ub[2 * t], b = ub[2 * t + 1];
            float4 pa = g_pts[a], pb = g_pts[b];
            float d = f3norm(pa.x - pb.x, pa.y - pb.y, pa.z - pb.z);
            float dd = d - s0[t];
            acc += ku[t] * dd * dd;
        }
        if (t < ndh) {
            float delta = torsion_angle(dih[4 * t], dih[4 * t + 1], dih[4 * t + 2], dih[4 * t + 3]);
            acc += kd[t] * (1.0f + cosf(nd[t] * delta - d0[t] * DEG2RAD));
        }
        if (t < ni) {
            float psi = torsion_angle(imp[4 * t], imp[4 * t + 1], imp[4 * t + 2], imp[4 * t + 3]);
            float dd = psi - p0[t] * DEG2RAD;
            acc += kp[t] * dd * dd;
        }
    } else {
        // ---- central restraint (flag is 0 in this dataset, but stay correct) ----
        if (central[0] != 0) {
            __shared__ float rx[256], ry[256], rz[256];
            float sx = 0.f, sy = 0.f, sz = 0.f;
            for (int i = tid; i < n; i += 256) {
                float4 p = g_pts[i];
                sx += p.x; sy += p.y; sz += p.z;
            }
            rx[tid] = sx; ry[tid] = sy; rz[tid] = sz;
            __syncthreads();
            for (int s = 128; s > 0; s >>= 1) {
                if (tid < s) {
                    rx[tid] += rx[tid + s];
                    ry[tid] += ry[tid + s];
                    rz[tid] += rz[tid + s];
                }
                __syncthreads();
            }
            float mx = rx[0] / (float)n, my = ry[0] / (float)n, mz = rz[0] / (float)n;
            for (int i = tid; i < n; i += 256) {
                float4 p = g_pts[i];
                float dx = p.x - mx, dy = p.y - my, dz = p.z - mz;
                acc += 0.1f * (dx * dx + dy * dy + dz * dz);
            }
        }
    }

    commitBlock(acc, out);
}

static inline int imax2(int a, int b) { return a > b ? a : b; }

extern "C" void kernel_launch(void* const* d_in, const int* in_sizes, int n_in,
                              void* d_out, int out_size) {
    const float* x    = (const float*)d_in[0];
    const float* kb   = (const float*)d_in[1];
    const float* b0   = (const float*)d_in[2];
    const float* kt   = (const float*)d_in[3];
    const float* t0   = (const float*)d_in[4];
    const float* ku   = (const float*)d_in[5];
    const float* s0   = (const float*)d_in[6];
    const float* kd   = (const float*)d_in[7];
    const float* nd   = (const float*)d_in[8];
    const float* d0   = (const float*)d_in[9];
    const float* kp   = (const float*)d_in[10];
    const float* p0   = (const float*)d_in[11];
    const float* eps  = (const float*)d_in[12];
    const float* rmin = (const float*)d_in[13];
    const float* kqq  = (const float*)d_in[14];
    const int* bond   = (const int*)d_in[15];
    const int* ang    = (const int*)d_in[16];
    const int* ub     = (const int*)d_in[17];
    const int* dih    = (const int*)d_in[18];
    const int* imp    = (const int*)d_in[19];
    const int* cen    = (const int*)d_in[20];

    int n   = in_sizes[0] / 3;
    int nb  = in_sizes[15] / 2;
    int na  = in_sizes[16] / 3;
    int nu  = in_sizes[17] / 2;
    int ndh = in_sizes[18] / 4;
    int ni  = in_sizes[19] / 4;

    k_pack<<<(n + 255) / 256, 256>>>(x, n);

    int nrows = n - 1;
    int nbB = (nrows + 1) / 2;
    int maxc = imax2(imax2(nb, na), imax2(nu, imax2(ndh, ni)));
    int bondB = (maxc + 255) / 256;
    int total = nbB + bondB + 1;

    k_main<<<total, 256>>>(eps, rmin, kqq, n, nbB,
                           bond, kb, b0, nb,
                           ang, kt, t0, na,
                           ub, ku, s0, nu,
                           dih, kd, nd, d0, ndh,
                           imp, kp, p0, ni,
                           bondB, cen,
                           (float*)d_out);
}